// round 15
// baseline (speedup 1.0000x reference)
#include <cuda_runtime.h>
#include <stdint.h>

// Problem constants (fixed by setup_inputs)
#define BB     128
#define CC     3
#define HH     224
#define WW     224
#define NP     98        // patches per batch image
#define PSZ    16        // patch size
#define MW     7         // mask words per image row: 224/32
#define STRIPE 16        // rows per block
#define ROW_B       (WW * 4)              // 896 bytes per row
#define CH_STRIPE_B (STRIPE * ROW_B)      // 14336 bytes per channel-stripe
#define TILE_B      (CC * CH_STRIPE_B)    // 43008 bytes per block tile
#define PLANE_B     (HH * ROW_B)          // 200704 bytes per channel plane
#define THREADS     224                   // thread = image column x

// ---------------------------------------------------------------------------
// TMA-bulk streaming kernel. grid = (14, 128), block = 224 threads.
//   1. issue 3x cp.async.bulk (g->s), 14336 B each, one mbarrier (43008 B tx)
//   2. rasterize the 98 patches into a 16x7-word smem bitmask (overlaps TMA)
//   3. acquire-wait the mbarrier; zero masked pixels in smem (STS only)
//   4. fence.proxy.async; 3x cp.async.bulk (s->g); wait_group before exit
// ---------------------------------------------------------------------------
__global__ __launch_bounds__(THREADS) void occlude_tma_kernel(
        const float* __restrict__ img,
        const int*   __restrict__ px,
        const int*   __restrict__ py,
        float*       __restrict__ out) {
    __shared__ alignas(128) float data[TILE_B / 4];      // 10752 floats (42 KB)
    __shared__ unsigned mask[STRIPE * MW];               // 112 words
    __shared__ alignas(8) unsigned long long mbar;

    const int tid = threadIdx.x;
    const int b   = blockIdx.y;
    const int r0  = blockIdx.x * STRIPE;

    const uint32_t s_data = (uint32_t)__cvta_generic_to_shared(data);
    const uint32_t s_mbar = (uint32_t)__cvta_generic_to_shared(&mbar);

    // --- init: clear mask, init mbarrier ---
    if (tid < STRIPE * MW) mask[tid] = 0u;
    if (tid == 0) {
        asm volatile("mbarrier.init.shared.b64 [%0], 1;" :: "r"(s_mbar) : "memory");
    }
    __syncthreads();

    // --- issue TMA bulk loads (3 channel-stripes) ---
    if (tid == 0) {
        asm volatile("mbarrier.arrive.expect_tx.shared.b64 _, [%0], %1;"
                     :: "r"(s_mbar), "r"(TILE_B) : "memory");
        const char* src = (const char*)img
                        + (size_t)b * CC * PLANE_B + (size_t)r0 * ROW_B;
        #pragma unroll
        for (int c = 0; c < CC; c++) {
            asm volatile(
                "cp.async.bulk.shared::cluster.global.mbarrier::complete_tx::bytes "
                "[%0], [%1], %2, [%3];"
                :: "r"(s_data + c * CH_STRIPE_B),
                   "l"(src + (size_t)c * PLANE_B),
                   "r"(CH_STRIPE_B), "r"(s_mbar)
                : "memory");
        }
    }

    // --- rasterize intersecting patches into the smem mask (overlaps TMA) ---
    if (tid < NP) {
        int x = px[b * NP + tid];               // top row (H dim)
        int lo_r = max(x, r0);
        int hi_r = min(x + PSZ, r0 + STRIPE);   // exclusive
        if (lo_r < hi_r) {
            int y  = py[b * NP + tid];          // left col (W dim)
            int w0 = y >> 5;
            int sh = y & 31;
            unsigned long long bits = 0xFFFFull << sh;   // spans <=2 words
            unsigned blo = (unsigned)bits;
            unsigned bhi = (unsigned)(bits >> 32);
            for (int rr = lo_r; rr < hi_r; rr++) {
                unsigned* row = mask + (rr - r0) * MW + w0;
                atomicOr(row, blo);
                if (bhi) atomicOr(row + 1, bhi);
            }
        }
    }
    __syncthreads();   // mask complete

    // --- wait for TMA load completion (acquire orders TMA writes vs our STS) ---
    asm volatile(
        "{\n\t"
        ".reg .pred p;\n\t"
        "WAIT_%=:\n\t"
        "mbarrier.try_wait.parity.acquire.cta.shared::cta.b64 p, [%0], 0, 0x989680;\n\t"
        "@!p bra WAIT_%=;\n\t"
        "}"
        :: "r"(s_mbar) : "memory");

    // --- zero masked pixels in smem: thread = column x, 16 rows x 3 channels ---
    {
        const int wi = tid >> 5;
        const int sh = tid & 31;
        #pragma unroll
        for (int r = 0; r < STRIPE; r++) {
            if ((mask[r * MW + wi] >> sh) & 1u) {
                data[0 * (STRIPE * WW) + r * WW + tid] = 0.0f;
                data[1 * (STRIPE * WW) + r * WW + tid] = 0.0f;
                data[2 * (STRIPE * WW) + r * WW + tid] = 0.0f;
            }
        }
    }
    __syncthreads();   // all zero-writes visible to tid 0 (generic proxy)

    // --- TMA bulk stores (3 channel-stripes) ---
    if (tid == 0) {
        asm volatile("fence.proxy.async.shared::cta;" ::: "memory");
        char* dst = (char*)out + (size_t)b * CC * PLANE_B + (size_t)r0 * ROW_B;
        #pragma unroll
        for (int c = 0; c < CC; c++) {
            asm volatile(
                "cp.async.bulk.global.shared::cta.bulk_group [%0], [%1], %2;"
                :: "l"(dst + (size_t)c * PLANE_B),
                   "r"(s_data + c * CH_STRIPE_B),
                   "r"(CH_STRIPE_B)
                : "memory");
        }
        asm volatile("cp.async.bulk.commit_group;" ::: "memory");
        // smem may not be reused until the bulk reads complete
        asm volatile("cp.async.bulk.wait_group.read 0;" ::: "memory");
    }
    __syncthreads();
}

// ---------------------------------------------------------------------------
extern "C" void kernel_launch(void* const* d_in, const int* in_sizes, int n_in,
                              void* d_out, int out_size) {
    const float* imgs = (const float*)d_in[0];
    const int*   px   = (const int*)d_in[1];
    const int*   py   = (const int*)d_in[2];
    float*       out  = (float*)d_out;

    dim3 grid(HH / STRIPE, BB);   // (14, 128) = 1792 blocks
    occlude_tma_kernel<<<grid, THREADS>>>(imgs, px, py, out);
}